// round 6
// baseline (speedup 1.0000x reference)
#include <cuda_runtime.h>
#include <cuda_bf16.h>
#include <mma.h>

using namespace nvcuda;

namespace {
constexpr int B_ = 8, V_ = 64, T_ = 256, T1_ = 257, D_ = 256, H_ = 8, DH_ = 32;
constexpr float EPS = 1e-5f;
constexpr int LDA = 264;                 // bf16 elems per sA row (528B)
constexpr int LDW = 72;                  // bf16 elems per weight-chunk row (144B)
// k_main dynamic smem layout (bytes): sA[64][LDA] + 2 weight chunk buffers
constexpr int OFF_W0 = 64 * LDA * 2;                 // 33792
constexpr int OFF_W1 = OFF_W0 + 256 * LDW * 2;       // +36864
constexpr int SM_MAIN = OFF_W1 + 256 * LDW * 2;      // 107520 (2 blocks/SM)
constexpr int SM_QK = 2 * 64 * LDA * 2;              // 67584
}

// ---------------- scratch (device globals) ----------------------------------
__device__ __nv_bfloat16 g_wb[768 * 256];      // bf16 w_qkv
__device__ __nv_bfloat16 g_wp[256 * 256];      // bf16 w_proj
__device__ __nv_bfloat16 g_xn0[512 * 256];     // LN(x[:,:,0]) bf16
__device__ __nv_bfloat16 g_xbar[512 * 256];    // masked-mean of LN(x) bf16
__device__ float g_q[512 * 256];
__device__ float g_k[512 * 256];
__device__ __nv_bfloat16 g_attn[8 * 8 * 64 * 64];
__device__ int g_mask_mode;

__device__ __forceinline__ float warp_sum(float v) {
#pragma unroll
    for (int o = 16; o; o >>= 1) v += __shfl_xor_sync(0xffffffffu, v, o);
    return v;
}

__device__ __forceinline__ bool mask_at(const void* m, int mode, long i) {
    if (mode == 0) return ((const unsigned char*)m)[i] != 0;
    if (mode == 1) return ((const int*)m)[i] != 0;
    return ((const float*)m)[i] != 0.0f;
}

__device__ __forceinline__ void cp16(void* s, const void* g) {
    unsigned sa = (unsigned)__cvta_generic_to_shared(s);
    asm volatile("cp.async.cg.shared.global [%0], [%1], 16;\n" :: "r"(sa), "l"(g));
}
__device__ __forceinline__ void cp_commit() {
    asm volatile("cp.async.commit_group;\n");
}
template <int N>
__device__ __forceinline__ void cp_wait() {
    asm volatile("cp.async.wait_group %0;\n" :: "n"(N));
}

// ---------------- raw tensor-core primitives ---------------------------------
__device__ __forceinline__ void ldsm_x4(unsigned r[4], const __nv_bfloat16* p) {
    unsigned a = (unsigned)__cvta_generic_to_shared(p);
    asm volatile("ldmatrix.sync.aligned.m8n8.x4.shared.b16 {%0,%1,%2,%3}, [%4];"
                 : "=r"(r[0]), "=r"(r[1]), "=r"(r[2]), "=r"(r[3]) : "r"(a));
}
__device__ __forceinline__ void ldsm_x4t(unsigned r[4], const __nv_bfloat16* p) {
    unsigned a = (unsigned)__cvta_generic_to_shared(p);
    asm volatile("ldmatrix.sync.aligned.m8n8.x4.trans.shared.b16 {%0,%1,%2,%3}, [%4];"
                 : "=r"(r[0]), "=r"(r[1]), "=r"(r[2]), "=r"(r[3]) : "r"(a));
}
__device__ __forceinline__ void mma_bf16(float c[4], const unsigned a[4], const unsigned* b) {
    asm volatile(
        "mma.sync.aligned.m16n8k16.row.col.f32.bf16.bf16.f32 "
        "{%0,%1,%2,%3},{%4,%5,%6,%7},{%8,%9},{%0,%1,%2,%3};"
        : "+f"(c[0]), "+f"(c[1]), "+f"(c[2]), "+f"(c[3])
        : "r"(a[0]), "r"(a[1]), "r"(a[2]), "r"(a[3]), "r"(b[0]), "r"(b[1]));
}

// ---------------- K0: detect obs_mask storage layout ------------------------
__global__ void k_detect(const unsigned char* m) {
    __shared__ int bad_i32, bad_f32;
    if (threadIdx.x == 0) { bad_i32 = 0; bad_f32 = 0; }
    __syncthreads();
    const unsigned int* w = (const unsigned int*)m;
    int bi = 0, bf = 0;
    for (int i = threadIdx.x; i < (B_ * V_ * T_) / 4; i += blockDim.x) {
        unsigned int x = w[i];
        if (x > 1u) bi = 1;
        if (x != 0u && x != 0x3F800000u) bf = 1;
    }
    if (bi) atomicOr(&bad_i32, 1);
    if (bf) atomicOr(&bad_f32, 1);
    __syncthreads();
    if (threadIdx.x == 0)
        g_mask_mode = (!bad_i32) ? 1 : ((!bad_f32) ? 2 : 0);
}

// ---------------- K1: convert weights to bf16 --------------------------------
__global__ void k_convert(const float* __restrict__ wqkv, const float* __restrict__ wproj) {
    int i = blockIdx.x * blockDim.x + threadIdx.x;
    if (i < 768 * 256) g_wb[i] = __float2bfloat16(wqkv[i]);
    else               g_wp[i - 768 * 256] = __float2bfloat16(wproj[i - 768 * 256]);
}

// ---------------- K2: xbar (masked mean of LN) + xn0 -------------------------
__global__ void k_xbar(const float* __restrict__ x, const void* __restrict__ mask,
                       const float* __restrict__ lnw, const float* __restrict__ lnb) {
    int bv = blockIdx.x;
    int w = threadIdx.x >> 5, lane = threadIdx.x & 31;
    int mode = g_mask_mode;

    float lw[8], lb[8], acc[8];
#pragma unroll
    for (int j = 0; j < 8; j++) {
        lw[j] = lnw[lane + 32 * j];
        lb[j] = lnb[lane + 32 * j];
        acc[j] = 0.0f;
    }
    float cnt = 0.0f;

    for (int t = w; t < T1_; t += 8) {
        const float* row = x + ((size_t)bv * T1_ + t) * D_;
        float r[8];
#pragma unroll
        for (int j = 0; j < 8; j++) r[j] = row[lane + 32 * j];
        float s = 0.0f;
#pragma unroll
        for (int j = 0; j < 8; j++) s += r[j];
        s = warp_sum(s);
        float mu = s * (1.0f / 256.0f);
        float v = 0.0f;
#pragma unroll
        for (int j = 0; j < 8; j++) { float d = r[j] - mu; v += d * d; }
        v = warp_sum(v);
        float rs = rsqrtf(v * (1.0f / 256.0f) + EPS);

        bool m = (t == 0) ? true : mask_at(mask, mode, (long)bv * T_ + (t - 1));
        if (m) {
#pragma unroll
            for (int j = 0; j < 8; j++)
                acc[j] += (r[j] - mu) * rs * lw[j] + lb[j];
            cnt += 1.0f;
        }
        if (t == 0) {
#pragma unroll
            for (int j = 0; j < 8; j++)
                g_xn0[bv * D_ + lane + 32 * j] =
                    __float2bfloat16((r[j] - mu) * rs * lw[j] + lb[j]);
        }
    }

    __shared__ float sAcc[8][256];
    __shared__ float sCnt[8];
#pragma unroll
    for (int j = 0; j < 8; j++) sAcc[w][lane + 32 * j] = acc[j];
    if (lane == 0) sCnt[w] = cnt;
    __syncthreads();

    int d = threadIdx.x;
    float tot = 0.0f, c = 0.0f;
#pragma unroll
    for (int i = 0; i < 8; i++) { tot += sAcc[i][d]; c += sCnt[i]; }
    c = fmaxf(c, 1.0f);
    g_xbar[bv * D_ + d] = __float2bfloat16(tot / c);
}

// ---------------- K3: q = xn0 @ Wq^T, k = xbar @ Wk^T ------------------------
__global__ void k_qk() {
    extern __shared__ char smem[];
    __nv_bfloat16* sA = (__nv_bfloat16*)smem;
    __nv_bfloat16* sB = sA + 64 * LDA;

    int bid = blockIdx.x;
    int mat = bid >> 5, tile = bid & 31;
    int tr = tile >> 2, tc = tile & 3;
    const __nv_bfloat16* Ag = mat == 0 ? g_xn0 : g_xbar;
    const __nv_bfloat16* Wg = g_wb + (size_t)mat * 256 * 256;
    float* Cg = mat == 0 ? g_q : g_k;

    int tid = threadIdx.x;
    for (int idx = tid; idx < 64 * 32; idx += 256) {
        int r = idx >> 5, c = idx & 31;
        *(uint4*)(sA + r * LDA + c * 8) = *(const uint4*)(Ag + (size_t)(tr * 64 + r) * 256 + c * 8);
        *(uint4*)(sB + r * LDA + c * 8) = *(const uint4*)(Wg + (size_t)(tc * 64 + r) * 256 + c * 8);
    }
    __syncthreads();

    int w = tid >> 5, rt = w & 3, cg = w >> 2;
    wmma::fragment<wmma::accumulator, 16, 16, 16, float> acc[2];
    wmma::fill_fragment(acc[0], 0.0f);
    wmma::fill_fragment(acc[1], 0.0f);
#pragma unroll
    for (int k = 0; k < 16; k++) {
        wmma::fragment<wmma::matrix_a, 16, 16, 16, __nv_bfloat16, wmma::row_major> af;
        wmma::load_matrix_sync(af, sA + (rt * 16) * LDA + k * 16, LDA);
#pragma unroll
        for (int j = 0; j < 2; j++) {
            wmma::fragment<wmma::matrix_b, 16, 16, 16, __nv_bfloat16, wmma::col_major> bf;
            wmma::load_matrix_sync(bf, sB + (cg * 32 + j * 16) * LDA + k * 16, LDA);
            wmma::mma_sync(acc[j], af, bf, acc[j]);
        }
    }
#pragma unroll
    for (int j = 0; j < 2; j++)
        wmma::store_matrix_sync(
            Cg + (size_t)(tr * 64 + rt * 16) * 256 + tc * 64 + cg * 32 + j * 16,
            acc[j], 256, wmma::mem_row_major);
}

// ---------------- K4: attention softmax (per b,h: 64x64) --------------------
__global__ void k_attn() {
    int b = blockIdx.x / H_, h = blockIdx.x % H_;
    __shared__ float qh[64][32], kh[64][32], sc[64][64];
    int tid = threadIdx.x;

    for (int i = tid; i < 64 * 32; i += 128) {
        int vq = i >> 5, d = i & 31;
        qh[vq][d] = g_q[(size_t)(b * 64 + vq) * D_ + h * 32 + d];
        kh[vq][d] = g_k[(size_t)(b * 64 + vq) * D_ + h * 32 + d];
    }
    __syncthreads();

    const float scale = rsqrtf((float)DH_);
    for (int i = tid; i < 64 * 64; i += 128) {
        int vq = i >> 6, vk = i & 63;
        float s = 0.0f;
#pragma unroll
        for (int d = 0; d < 32; d++) s += qh[vq][d] * kh[vk][d];
        sc[vq][vk] = s * scale;
    }
    __syncthreads();

    if (tid < 64) {
        int vq = tid;
        float mx = -1e30f;
        for (int vk = 0; vk < 64; vk++) mx = fmaxf(mx, sc[vq][vk]);
        float sum = 0.0f;
        for (int vk = 0; vk < 64; vk++) { float e = expf(sc[vq][vk] - mx); sc[vq][vk] = e; sum += e; }
        float inv = 1.0f / sum;
        __nv_bfloat16* dst = g_attn + (size_t)((b * H_ + h) * 64 + vq) * 64;
        for (int vk = 0; vk < 64; vk++) dst[vk] = __float2bfloat16(sc[vq][vk] * inv);
    }
}

// ---------------- k_main helpers (256-thread variants) -----------------------
__device__ __forceinline__ void load_wchunk(__nv_bfloat16* sW,
                                            const __nv_bfloat16* __restrict__ Wg,
                                            int kc, int tid) {
#pragma unroll
    for (int i = 0; i < 8; i++) {
        int idx = tid + i * 256;            // 0..2047
        int n = idx >> 3, seg = idx & 7;
        cp16(sW + n * LDW + seg * 8, Wg + (size_t)n * 256 + kc * 64 + seg * 8);
    }
    cp_commit();
}

// C(64x256) = A(64x256 bf16 in sA) @ W(256x256)^T.
// 8 warps: rb = w>>2 (0..1, 32 rows), cb = w&3 (64 cols). acc[2][8][4].
// Caller must have issued load_wchunk(sW0, Wg, 0) + commit already.
__device__ __forceinline__ void gemm_k256(const __nv_bfloat16* __restrict__ Wg,
                                          const __nv_bfloat16* sA,
                                          __nv_bfloat16* sW0, __nv_bfloat16* sW1,
                                          float acc[2][8][4], int tid, int lane) {
    int w = tid >> 5, rb = w >> 2, cb = w & 3;
#pragma unroll
    for (int i = 0; i < 2; i++)
#pragma unroll
        for (int j = 0; j < 8; j++)
#pragma unroll
            for (int e = 0; e < 4; e++) acc[i][j][e] = 0.0f;

    int arow = lane & 15, acolb = (lane >> 4) << 3;
    int brow = (lane & 7) + ((lane & 16) ? 8 : 0), bcolb = (lane & 8) ? 8 : 0;

#pragma unroll
    for (int kc = 0; kc < 4; kc++) {
        const __nv_bfloat16* cur = (kc & 1) ? sW1 : sW0;
        __nv_bfloat16* nxt = (kc & 1) ? sW0 : sW1;
        if (kc < 3) { load_wchunk(nxt, Wg, kc + 1, tid); cp_wait<1>(); }
        else        { cp_wait<0>(); }
        __syncthreads();
#pragma unroll
        for (int s = 0; s < 4; s++) {
            int k0 = s * 16;
            unsigned a0[4], a1[4];
            ldsm_x4(a0, sA + (rb * 32 + arow) * LDA + kc * 64 + k0 + acolb);
            ldsm_x4(a1, sA + (rb * 32 + 16 + arow) * LDA + kc * 64 + k0 + acolb);
#pragma unroll
            for (int jj = 0; jj < 4; jj++) {
                unsigned bb[4];
                ldsm_x4(bb, cur + (cb * 64 + jj * 16 + brow) * LDW + k0 + bcolb);
                mma_bf16(acc[0][jj * 2 + 0], a0, bb + 0);
                mma_bf16(acc[0][jj * 2 + 1], a0, bb + 2);
                mma_bf16(acc[1][jj * 2 + 0], a1, bb + 0);
                mma_bf16(acc[1][jj * 2 + 1], a1, bb + 2);
            }
        }
        __syncthreads();
    }
}

// convert f32 accumulators -> bf16 directly into sA (no f32 staging)
__device__ __forceinline__ void store_acc_bf16(float acc[2][8][4], __nv_bfloat16* sA,
                                               int tid, int lane) {
    int w = tid >> 5, rb = w >> 2, cb = w & 3;
    int r0 = rb * 32 + (lane >> 2), c0 = cb * 64 + (lane & 3) * 2;
#pragma unroll
    for (int i = 0; i < 2; i++)
#pragma unroll
        for (int jj = 0; jj < 8; jj++) {
            __nv_bfloat162 lo = __floats2bfloat162_rn(acc[i][jj][0], acc[i][jj][1]);
            __nv_bfloat162 hi = __floats2bfloat162_rn(acc[i][jj][2], acc[i][jj][3]);
            *(__nv_bfloat162*)(sA + (r0 + i * 16) * LDA + c0 + jj * 8) = lo;
            *(__nv_bfloat162*)(sA + (r0 + i * 16 + 8) * LDA + c0 + jj * 8) = hi;
        }
}

// ---------------- K5: fused LN + V-GEMM + attn-mix + proj + residual ---------
// One block per (b, t): 64 rows x 256 cols. 256 threads, 2 blocks/SM.
__global__ void __launch_bounds__(256, 2)
k_main(const float* __restrict__ x, const float* __restrict__ lnw,
       const float* __restrict__ lnb, const float* __restrict__ bproj,
       float* __restrict__ out) {
    extern __shared__ char smem[];
    __nv_bfloat16* sA  = (__nv_bfloat16*)smem;               // [64][LDA]
    __nv_bfloat16* sW0 = (__nv_bfloat16*)(smem + OFF_W0);
    __nv_bfloat16* sW1 = (__nv_bfloat16*)(smem + OFF_W1);

    int b = blockIdx.x / T1_, t = blockIdx.x % T1_;
    int tid = threadIdx.x, w = tid >> 5, lane = tid & 31;

    // kick off Wv chunk0 before LN (fully hidden)
    const __nv_bfloat16* Wv = g_wb + (size_t)512 * 256;
    load_wchunk(sW0, Wv, 0, tid);

    // ---- LayerNorm: 64 rows -> sA bf16 ----
    for (int v = w; v < 64; v += 8) {
        const float* rowp = x + ((size_t)(b * 64 + v) * T1_ + t) * D_ + lane * 8;
        float4 p0 = *(const float4*)rowp;
        float4 p1 = *(const float4*)(rowp + 4);
        float rr[8] = {p0.x, p0.y, p0.z, p0.w, p1.x, p1.y, p1.z, p1.w};
        float s = 0.0f;
#pragma unroll
        for (int j = 0; j < 8; j++) s += rr[j];
        s = warp_sum(s);
        float mu = s * (1.0f / 256.0f);
        float var = 0.0f;
#pragma unroll
        for (int j = 0; j < 8; j++) { float d = rr[j] - mu; var += d * d; }
        var = warp_sum(var);
        float rs = rsqrtf(var * (1.0f / 256.0f) + EPS);
        float4 w0 = *(const float4*)(lnw + lane * 8);
        float4 w1 = *(const float4*)(lnw + lane * 8 + 4);
        float4 b0 = *(const float4*)(lnb + lane * 8);
        float4 b1 = *(const float4*)(lnb + lane * 8 + 4);
        float lwv[8] = {w0.x, w0.y, w0.z, w0.w, w1.x, w1.y, w1.z, w1.w};
        float lbv[8] = {b0.x, b0.y, b0.z, b0.w, b1.x, b1.y, b1.z, b1.w};
#pragma unroll
        for (int j = 0; j < 4; j++) {
            __nv_bfloat162 hv = __floats2bfloat162_rn(
                (rr[2 * j] - mu) * rs * lwv[2 * j] + lbv[2 * j],
                (rr[2 * j + 1] - mu) * rs * lwv[2 * j + 1] + lbv[2 * j + 1]);
            *(__nv_bfloat162*)(sA + v * LDA + lane * 8 + 2 * j) = hv;
        }
    }
    __syncthreads();

    // ---- vf = xn @ Wv^T ----
    {
        float acc[2][8][4];
        gemm_k256(Wv, sA, sW0, sW1, acc, tid, lane);
        // prefetch proj chunk0 while we convert + mix (sW0 free now)
        load_wchunk(sW0, g_wp, 0, tid);
        store_acc_bf16(acc, sA, tid, lane);   // vf (bf16) into sA
    }
    __syncthreads();

    // ---- attn mixing: warp w = head h, tile 64x32 ----
    {
        int h = w;
        float mc[4][4][4];
#pragma unroll
        for (int a = 0; a < 4; a++)
#pragma unroll
            for (int c = 0; c < 4; c++)
#pragma unroll
                for (int e = 0; e < 4; e++) mc[a][c][e] = 0.0f;

        const __nv_bfloat16* att = g_attn + (size_t)(b * H_ + h) * 64 * 64;
        int lr = lane >> 2, lc = (lane & 3) * 2;
        int trow = lane & 15, tcolb = (lane & 16) ? 8 : 0;
#pragma unroll
        for (int kt = 0; kt < 4; kt++) {
            int k0 = kt * 16;
            unsigned bb0[4], bb1[4];
            ldsm_x4t(bb0, sA + (k0 + trow) * LDA + h * 32 + tcolb);
            ldsm_x4t(bb1, sA + (k0 + trow) * LDA + h * 32 + 16 + tcolb);
#pragma unroll
            for (int rt = 0; rt < 4; rt++) {
                const __nv_bfloat16* ap = att + (size_t)(rt * 16 + lr) * 64 + k0 + lc;
                unsigned aa[4];
                aa[0] = *(const unsigned*)ap;
                aa[1] = *(const unsigned*)(ap + 8 * 64);
                aa[2] = *(const unsigned*)(ap + 8);
                aa[3] = *(const unsigned*)(ap + 8 * 64 + 8);
                mma_bf16(mc[rt][0], aa, bb0 + 0);
                mma_bf16(mc[rt][1], aa, bb0 + 2);
                mma_bf16(mc[rt][2], aa, bb1 + 0);
                mma_bf16(mc[rt][3], aa, bb1 + 2);
            }
        }
        // per-warp column band [h*32, h*32+32) is self-contained
        int r0 = lane >> 2, c0 = h * 32 + (lane & 3) * 2;
#pragma unroll
        for (int rt = 0; rt < 4; rt++)
#pragma unroll
            for (int jj = 0; jj < 4; jj++) {
                __nv_bfloat162 lo = __floats2bfloat162_rn(mc[rt][jj][0], mc[rt][jj][1]);
                __nv_bfloat162 hi = __floats2bfloat162_rn(mc[rt][jj][2], mc[rt][jj][3]);
                *(__nv_bfloat162*)(sA + (r0 + rt * 16) * LDA + c0 + jj * 8) = lo;
                *(__nv_bfloat162*)(sA + (r0 + rt * 16 + 8) * LDA + c0 + jj * 8) = hi;
            }
    }
    __syncthreads();

    // ---- proj = mixed @ Wp^T, epilogue straight from registers ----
    {
        float acc[2][8][4];
        gemm_k256(g_wp, sA, sW0, sW1, acc, tid, lane);

        int rb = w >> 2, cb = w & 3;
        int r0 = rb * 32 + (lane >> 2), c0 = cb * 64 + (lane & 3) * 2;
#pragma unroll
        for (int i = 0; i < 2; i++)
#pragma unroll
            for (int half = 0; half < 2; half++) {
                int rr = r0 + i * 16 + half * 8;
                size_t base = ((size_t)(b * 64 + rr) * T1_ + t) * D_;
#pragma unroll
                for (int jj = 0; jj < 8; jj++) {
                    size_t gi = base + c0 + jj * 8;
                    float2 xv = *(const float2*)(x + gi);
                    float2 o;
                    o.x = acc[i][jj][half * 2 + 0] + bproj[c0 + jj * 8] + xv.x;
                    o.y = acc[i][jj][half * 2 + 1] + bproj[c0 + jj * 8 + 1] + xv.y;
                    *(float2*)(out + gi) = o;
                }
            }
    }
}

// ---------------- launch ----------------------------------------------------
extern "C" void kernel_launch(void* const* d_in, const int* in_sizes, int n_in,
                              void* d_out, int out_size) {
    const float* x     = (const float*)d_in[0];
    const void*  mask  = d_in[1];
    const float* lnw   = (const float*)d_in[2];
    const float* lnb   = (const float*)d_in[3];
    const float* wqkv  = (const float*)d_in[4];
    const float* wproj = (const float*)d_in[5];
    const float* bproj = (const float*)d_in[6];
    float* out = (float*)d_out;

    cudaFuncSetAttribute(k_main, cudaFuncAttributeMaxDynamicSharedMemorySize, SM_MAIN);
    cudaFuncSetAttribute(k_qk, cudaFuncAttributeMaxDynamicSharedMemorySize, SM_QK);

    k_detect<<<1, 256>>>((const unsigned char*)mask);
    k_convert<<<1024, 256>>>(wqkv, wproj);
    k_xbar<<<B_ * V_, 256>>>(x, mask, lnw, lnb);
    k_qk<<<64, 256, SM_QK>>>();
    k_attn<<<B_ * H_, 128>>>();
    k_main<<<B_ * T1_, 256, SM_MAIN>>>(x, lnw, lnb, bproj, out);
}